// round 2
// baseline (speedup 1.0000x reference)
#include <cuda_runtime.h>
#include <cuda_bf16.h>
#include <math.h>

#define NNODES 100000
#define NEDGES 1600000
#define NLAB   200000
#define TOTE   (NEDGES + NNODES)

// ---------------- scratch (device globals; no allocation allowed) ----------------
__device__ int   g_deg[NNODES];
__device__ float g_dis[NNODES];
__device__ int   g_row[NNODES + 1];
__device__ int   g_cnt[NNODES];
__device__ int   g_bsum[128];
__device__ int   g_csr_src[TOTE];
__device__ float g_csr_w[TOTE];
__device__ float g_bufA[(size_t)NNODES * 128];
__device__ float g_bufB[(size_t)NNODES * 128];

// ---------------- f32x2 packed-FMA helpers (sm_100+ PTX) ----------------
__device__ __forceinline__ unsigned long long splat2(float a) {
    unsigned long long r;
    asm("mov.b64 %0, {%1, %1};" : "=l"(r) : "f"(a));
    return r;
}
__device__ __forceinline__ unsigned long long pack2(float lo, float hi) {
    unsigned long long r;
    asm("mov.b64 %0, {%1, %2};" : "=l"(r) : "f"(lo), "f"(hi));
    return r;
}
__device__ __forceinline__ void fma2(unsigned long long& c, unsigned long long a, unsigned long long b) {
    asm("fma.rn.f32x2 %0, %1, %2, %0;" : "+l"(c) : "l"(a), "l"(b));
}
union F2U { unsigned long long u; float2 f; };

// ---------------- CSR build ----------------
__global__ void k_init(void) {
    int i = blockIdx.x * blockDim.x + threadIdx.x;
    if (i < NNODES) { g_deg[i] = 1; g_cnt[i] = 0; }   // self loop counted
}

__global__ void k_count(const int* __restrict__ ei) {
    int e = blockIdx.x * blockDim.x + threadIdx.x;
    if (e < NEDGES) atomicAdd(&g_deg[ei[NEDGES + e]], 1);
}

__global__ void k_dis(void) {
    int i = blockIdx.x * blockDim.x + threadIdx.x;
    if (i < NNODES) g_dis[i] = rsqrtf((float)g_deg[i]);
}

__global__ void k_scan_blocks(void) {
    __shared__ int sh[1024];
    int i = blockIdx.x * 1024 + threadIdx.x;
    int v = (i < NNODES) ? g_deg[i] : 0;
    sh[threadIdx.x] = v;
    __syncthreads();
    for (int off = 1; off < 1024; off <<= 1) {
        int t = (threadIdx.x >= off) ? sh[threadIdx.x - off] : 0;
        __syncthreads();
        sh[threadIdx.x] += t;
        __syncthreads();
    }
    if (i < NNODES) g_row[i] = sh[threadIdx.x] - v;   // exclusive
    if (threadIdx.x == 1023) g_bsum[blockIdx.x] = sh[1023];
}

__global__ void k_scan_sums(int nblocks) {
    if (threadIdx.x == 0) {
        int run = 0;
        for (int g = 0; g < nblocks; g++) {
            int v = g_bsum[g];
            g_bsum[g] = run;
            run += v;
        }
    }
}

__global__ void k_add_off(void) {
    int i = blockIdx.x * blockDim.x + threadIdx.x;
    if (i < NNODES) g_row[i] += g_bsum[i >> 10];
    if (i == 0) g_row[NNODES] = TOTE;
}

__global__ void k_fill_csr(const int* __restrict__ ei) {
    int idx = blockIdx.x * blockDim.x + threadIdx.x;
    if (idx >= TOTE) return;
    int s, d;
    if (idx < NEDGES) { s = ei[idx]; d = ei[NEDGES + idx]; }
    else              { s = d = idx - NEDGES; }
    int pos = g_row[d] + atomicAdd(&g_cnt[d], 1);
    g_csr_src[pos] = s;
    g_csr_w[pos]   = g_dis[s] * g_dis[d];
}

// ---------------- SGEMM: O[M,BN] = X[M,128] @ W[128,BN], f32x2 FFMA ----------------
template<int BN>
__global__ __launch_bounds__(256, 2)
void k_sgemm(const float* __restrict__ X, const float* __restrict__ W,
             float* __restrict__ O, int M) {
    constexpr int BK  = 8;
    constexpr int TN  = BN / 16;   // 8 (BN=128) or 4 (BN=64)
    constexpr int NP2 = TN / 2;    // accumulator pairs per row
    __shared__ float Xs[BK][132];
    __shared__ float Ws[BK][BN + 4];

    int tid  = threadIdx.x;
    int trow = tid >> 4;       // 0..15
    int tcol = tid & 15;       // 0..15
    int block_row = blockIdx.x * 128;

    unsigned long long acc[8][NP2];
#pragma unroll
    for (int i = 0; i < 8; i++)
#pragma unroll
        for (int j = 0; j < NP2; j++) acc[i][j] = 0ull;

    for (int k0 = 0; k0 < 128; k0 += BK) {
        // X tile -> transposed smem
        {
            int r    = tid >> 1;
            int seg  = (tid & 1) * 4;
            int grow = block_row + r;
            float4 xv = make_float4(0.f, 0.f, 0.f, 0.f);
            if (grow < M) xv = *(const float4*)(X + (size_t)grow * 128 + k0 + seg);
            Xs[seg + 0][r] = xv.x; Xs[seg + 1][r] = xv.y;
            Xs[seg + 2][r] = xv.z; Xs[seg + 3][r] = xv.w;
        }
        // W tile
        {
            constexpr int NV = BK * BN / 4;   // float4 loads
            if (tid < NV) {
                int kk = tid / (BN / 4);
                int c4 = (tid % (BN / 4)) * 4;
                float4 wv = *(const float4*)(W + (size_t)(k0 + kk) * BN + c4);
                *(float4*)&Ws[kk][c4] = wv;
            }
        }
        __syncthreads();
#pragma unroll
        for (int kk = 0; kk < BK; kk++) {
            float4 a0 = *(const float4*)&Xs[kk][trow * 8];
            float4 a1 = *(const float4*)&Xs[kk][trow * 8 + 4];
            float av[8] = {a0.x, a0.y, a0.z, a0.w, a1.x, a1.y, a1.z, a1.w};
            unsigned long long bb[NP2];
            float4 b0 = *(const float4*)&Ws[kk][tcol * TN];
            bb[0] = pack2(b0.x, b0.y);
            bb[1] = pack2(b0.z, b0.w);
            if constexpr (BN == 128) {
                float4 b1v = *(const float4*)&Ws[kk][tcol * TN + 4];
                bb[2] = pack2(b1v.x, b1v.y);
                bb[3] = pack2(b1v.z, b1v.w);
            }
#pragma unroll
            for (int i = 0; i < 8; i++) {
                unsigned long long as = splat2(av[i]);
#pragma unroll
                for (int j = 0; j < NP2; j++) fma2(acc[i][j], as, bb[j]);
            }
        }
        __syncthreads();
    }
#pragma unroll
    for (int i = 0; i < 8; i++) {
        int grow = block_row + trow * 8 + i;
        if (grow < M) {
#pragma unroll
            for (int j = 0; j < NP2; j++) {
                F2U u; u.u = acc[i][j];
                *(float2*)(O + (size_t)grow * BN + tcol * TN + j * 2) = u.f;
            }
        }
    }
}

// ---------------- aggregation: out[n] = relu?(b + sum_e w_e * h[src_e]) ----------------
template<bool RELU>
__global__ __launch_bounds__(256)
void k_aggregate128(const float* __restrict__ h, const float* __restrict__ bias,
                    float* __restrict__ out) {
    int w    = (blockIdx.x * blockDim.x + threadIdx.x) >> 5;
    int lane = threadIdx.x & 31;
    if (w >= NNODES) return;
    int beg = g_row[w], end = g_row[w + 1];
    float4 acc = make_float4(0.f, 0.f, 0.f, 0.f);
    for (int e = beg; e < end; e++) {
        int   s  = g_csr_src[e];
        float wt = g_csr_w[e];
        float4 v = *(const float4*)(h + (size_t)s * 128 + lane * 4);
        acc.x = fmaf(wt, v.x, acc.x);
        acc.y = fmaf(wt, v.y, acc.y);
        acc.z = fmaf(wt, v.z, acc.z);
        acc.w = fmaf(wt, v.w, acc.w);
    }
    float4 bb = *(const float4*)(bias + lane * 4);
    acc.x += bb.x; acc.y += bb.y; acc.z += bb.z; acc.w += bb.w;
    if (RELU) {
        acc.x = fmaxf(acc.x, 0.f); acc.y = fmaxf(acc.y, 0.f);
        acc.z = fmaxf(acc.z, 0.f); acc.w = fmaxf(acc.w, 0.f);
    }
    *(float4*)(out + (size_t)w * 128 + lane * 4) = acc;
}

template<bool RELU>
__global__ __launch_bounds__(256)
void k_aggregate64(const float* __restrict__ h, const float* __restrict__ bias,
                   float* __restrict__ out) {
    int w    = (blockIdx.x * blockDim.x + threadIdx.x) >> 5;
    int lane = threadIdx.x & 31;
    if (w >= NNODES) return;
    int beg = g_row[w], end = g_row[w + 1];
    float2 acc = make_float2(0.f, 0.f);
    for (int e = beg; e < end; e++) {
        int   s  = g_csr_src[e];
        float wt = g_csr_w[e];
        float2 v = *(const float2*)(h + (size_t)s * 64 + lane * 2);
        acc.x = fmaf(wt, v.x, acc.x);
        acc.y = fmaf(wt, v.y, acc.y);
    }
    float2 bb = *(const float2*)(bias + lane * 2);
    acc.x += bb.x; acc.y += bb.y;
    if (RELU) { acc.x = fmaxf(acc.x, 0.f); acc.y = fmaxf(acc.y, 0.f); }
    *(float2*)(out + (size_t)w * 64 + lane * 2) = acc;
}

// ---------------- decode: hidden = z[a]*z[b]; logits=sum; hidden_n = hidden/||hidden|| ----------------
__global__ __launch_bounds__(256)
void k_decode(const float* __restrict__ z, const int* __restrict__ eli,
              float* __restrict__ out) {
    int w    = (blockIdx.x * blockDim.x + threadIdx.x) >> 5;
    int lane = threadIdx.x & 31;
    if (w >= NLAB) return;
    int a = eli[w];
    int b = eli[NLAB + w];
    float2 za = *(const float2*)(z + (size_t)a * 64 + lane * 2);
    float2 zb = *(const float2*)(z + (size_t)b * 64 + lane * 2);
    float h0 = za.x * zb.x;
    float h1 = za.y * zb.y;
    float s  = h0 + h1;
    float q  = h0 * h0 + h1 * h1;
#pragma unroll
    for (int off = 16; off > 0; off >>= 1) {
        s += __shfl_xor_sync(0xFFFFFFFFu, s, off);
        q += __shfl_xor_sync(0xFFFFFFFFu, q, off);
    }
    float nrm = fmaxf(sqrtf(q), 1e-12f);
    float inv = 1.0f / nrm;
    *(float2*)(out + (size_t)w * 64 + lane * 2) = make_float2(h0 * inv, h1 * inv);
    if (lane == 0) out[(size_t)NLAB * 64 + w] = s;
}

// ---------------- launch ----------------
extern "C" void kernel_launch(void* const* d_in, const int* in_sizes, int n_in,
                              void* d_out, int out_size) {
    const float* x  = (const float*)d_in[0];
    const float* W1 = (const float*)d_in[1];
    const float* b1 = (const float*)d_in[2];
    const float* W2 = (const float*)d_in[3];
    const float* b2 = (const float*)d_in[4];
    const float* W3 = (const float*)d_in[5];
    const float* b3 = (const float*)d_in[6];
    const int*   ei  = (const int*)d_in[7];
    const int*   eli = (const int*)d_in[8];
    float* out = (float*)d_out;

    float* bufA = nullptr;
    float* bufB = nullptr;
    cudaGetSymbolAddress((void**)&bufA, g_bufA);
    cudaGetSymbolAddress((void**)&bufB, g_bufB);

    const int nscan = (NNODES + 1023) / 1024;   // 98

    // CSR build
    k_init<<<(NNODES + 255) / 256, 256>>>();
    k_count<<<(NEDGES + 255) / 256, 256>>>(ei);
    k_dis<<<(NNODES + 255) / 256, 256>>>();
    k_scan_blocks<<<nscan, 1024>>>();
    k_scan_sums<<<1, 32>>>(nscan);
    k_add_off<<<(NNODES + 255) / 256, 256>>>();
    k_fill_csr<<<(TOTE + 255) / 256, 256>>>(ei);

    const int gemm_grid = (NNODES + 127) / 128;     // 782
    const int agg_grid  = (NNODES * 32 + 255) / 256;  // 12500
    const int dec_grid  = (NLAB * 32 + 255) / 256;    // 25000

    // layer 1
    k_sgemm<128><<<gemm_grid, 256>>>(x, W1, bufB, NNODES);
    k_aggregate128<true><<<agg_grid, 256>>>(bufB, b1, bufA);
    // layer 2
    k_sgemm<128><<<gemm_grid, 256>>>(bufA, W2, bufB, NNODES);
    k_aggregate128<true><<<agg_grid, 256>>>(bufB, b2, bufA);
    // layer 3
    k_sgemm<64><<<gemm_grid, 256>>>(bufA, W3, bufB, NNODES);
    k_aggregate64<false><<<agg_grid, 256>>>(bufB, b3, bufA);
    // decode
    k_decode<<<dec_grid, 256>>>(bufA, eli, out);
}

// round 4
// speedup vs baseline: 1.0185x; 1.0185x over previous
#include <cuda_runtime.h>
#include <cuda_bf16.h>
#include <math.h>

#define NNODES 100000
#define NEDGES 1600000
#define NLAB   200000
#define TOTE   (NEDGES + NNODES)

// ---------------- scratch (device globals; no allocation allowed) ----------------
__device__ int   g_deg[NNODES];
__device__ float g_dis[NNODES];
__device__ int   g_row[NNODES + 1];
__device__ int   g_cnt[NNODES];
__device__ int   g_bsum[128];
__device__ int2  g_csr[TOTE];            // packed (src, weight-bits)
__device__ float g_bufA[(size_t)NNODES * 128];
__device__ float g_bufB[(size_t)NNODES * 128];

// ---------------- f32x2 packed-FMA helpers (sm_100+ PTX) ----------------
__device__ __forceinline__ unsigned long long pack2(float lo, float hi) {
    unsigned long long r;
    asm("mov.b64 %0, {%1, %2};" : "=l"(r) : "f"(lo), "f"(hi));
    return r;
}
__device__ __forceinline__ void fma2(unsigned long long& c, unsigned long long a, unsigned long long b) {
    asm("fma.rn.f32x2 %0, %1, %2, %0;" : "+l"(c) : "l"(a), "l"(b));
}
union F2U { unsigned long long u; float2 f; };

// ---------------- CSR build ----------------
__global__ void k_init(void) {
    int i = blockIdx.x * blockDim.x + threadIdx.x;
    if (i < NNODES) { g_deg[i] = 1; g_cnt[i] = 0; }   // self loop counted
}

__global__ void k_count(const int* __restrict__ ei) {
    int e = blockIdx.x * blockDim.x + threadIdx.x;
    if (e < NEDGES) atomicAdd(&g_deg[ei[NEDGES + e]], 1);
}

__global__ void k_dis(void) {
    int i = blockIdx.x * blockDim.x + threadIdx.x;
    if (i < NNODES) g_dis[i] = rsqrtf((float)g_deg[i]);
}

__global__ void k_scan_blocks(void) {
    __shared__ int sh[1024];
    int i = blockIdx.x * 1024 + threadIdx.x;
    int v = (i < NNODES) ? g_deg[i] : 0;
    sh[threadIdx.x] = v;
    __syncthreads();
    for (int off = 1; off < 1024; off <<= 1) {
        int t = (threadIdx.x >= off) ? sh[threadIdx.x - off] : 0;
        __syncthreads();
        sh[threadIdx.x] += t;
        __syncthreads();
    }
    if (i < NNODES) g_row[i] = sh[threadIdx.x] - v;   // exclusive
    if (threadIdx.x == 1023) g_bsum[blockIdx.x] = sh[1023];
}

__global__ void k_scan_sums(int nblocks) {
    if (threadIdx.x == 0) {
        int run = 0;
        for (int g = 0; g < nblocks; g++) {
            int v = g_bsum[g];
            g_bsum[g] = run;
            run += v;
        }
    }
}

__global__ void k_add_off(void) {
    int i = blockIdx.x * blockDim.x + threadIdx.x;
    if (i < NNODES) g_row[i] += g_bsum[i >> 10];
    if (i == 0) g_row[NNODES] = TOTE;
}

__global__ void k_fill_csr(const int* __restrict__ ei) {
    int idx = blockIdx.x * blockDim.x + threadIdx.x;
    if (idx >= TOTE) return;
    int s, d;
    if (idx < NEDGES) { s = ei[idx]; d = ei[NEDGES + idx]; }
    else              { s = d = idx - NEDGES; }
    int pos = g_row[d] + atomicAdd(&g_cnt[d], 1);
    float w = g_dis[s] * g_dis[d];
    g_csr[pos] = make_int2(s, __float_as_int(w));
}

// ---------------- SGEMM v2: O[M,BN] = X[M,128] @ W[128,BN] ----------------
// 128x{BN} block tile, BK=16, 256 threads, 8x(BN/16) per-thread tile.
// X stored duplicated in smem -> LDS.128 yields two splatted f32x2 operands.
// W stored pair-major u64 -> LDS.64 yields a ready f32x2 operand, conflict-free.
template<int BN>
__global__ __launch_bounds__(256, 2)
void k_sgemm(const float* __restrict__ X, const float* __restrict__ W,
             float* __restrict__ O, int M) {
    constexpr int BK = 16;
    constexpr int TN = BN / 16;          // 8 (BN=128) or 4 (BN=64)
    constexpr int NP = TN / 2;           // f32x2 pairs per row: 4 or 2
    __shared__ float Xd[BK][260];                      // duplicated row: 256 used (+4 pad, keeps 16B align)
    __shared__ unsigned long long Wp[BK][NP][16];      // pair-major

    int tid  = threadIdx.x;
    int trow = tid >> 4;       // 0..15
    int tcol = tid & 15;       // 0..15
    int brow = blockIdx.x * 128;

    unsigned long long acc[8][NP] = {};

    for (int k0 = 0; k0 < 128; k0 += BK) {
        // X tile: 128 rows x 16 cols = 512 float4 loads, duplicated store
#pragma unroll
        for (int b = 0; b < 2; b++) {
            int idx = tid * 2 + b;
            int r   = idx >> 2;
            int c4  = (idx & 3) * 4;
            int gr  = brow + r;
            float4 xv = make_float4(0.f, 0.f, 0.f, 0.f);
            if (gr < M) xv = *(const float4*)(X + (size_t)gr * 128 + k0 + c4);
            *(float2*)&Xd[c4 + 0][2 * r] = make_float2(xv.x, xv.x);
            *(float2*)&Xd[c4 + 1][2 * r] = make_float2(xv.y, xv.y);
            *(float2*)&Xd[c4 + 2][2 * r] = make_float2(xv.z, xv.z);
            *(float2*)&Xd[c4 + 3][2 * r] = make_float2(xv.w, xv.w);
        }
        // W tile: BK x BN floats -> pair-major
        {
            constexpr int WV = BK * BN / 4;      // 512 or 256
#pragma unroll
            for (int b = 0; b < WV / 256; b++) {
                int idx = tid + b * 256;
                int kk  = idx / (BN / 4);
                int c4  = idx % (BN / 4);
                float4 wv = *(const float4*)(W + (size_t)(k0 + kk) * BN + c4 * 4);
                int tc = (c4 * 4) / TN;
                int jp = ((c4 * 4) % TN) / 2;
                Wp[kk][jp + 0][tc] = pack2(wv.x, wv.y);
                Wp[kk][jp + 1][tc] = pack2(wv.z, wv.w);
            }
        }
        __syncthreads();
#pragma unroll
        for (int kk = 0; kk < BK; kk++) {
            ulonglong2 aA = *(const ulonglong2*)&Xd[kk][trow * 16 + 0];
            ulonglong2 aB = *(const ulonglong2*)&Xd[kk][trow * 16 + 4];
            ulonglong2 aC = *(const ulonglong2*)&Xd[kk][trow * 16 + 8];
            ulonglong2 aD = *(const ulonglong2*)&Xd[kk][trow * 16 + 12];
            unsigned long long as[8] = {aA.x, aA.y, aB.x, aB.y, aC.x, aC.y, aD.x, aD.y};
            unsigned long long bb[NP];
#pragma unroll
            for (int j = 0; j < NP; j++) bb[j] = Wp[kk][j][tcol];
#pragma unroll
            for (int i = 0; i < 8; i++)
#pragma unroll
                for (int j = 0; j < NP; j++) fma2(acc[i][j], as[i], bb[j]);
        }
        __syncthreads();
    }
#pragma unroll
    for (int i = 0; i < 8; i++) {
        int gr = brow + trow * 8 + i;
        if (gr < M) {
#pragma unroll
            for (int j = 0; j < NP; j += 2) {
                F2U u0, u1; u0.u = acc[i][j]; u1.u = acc[i][j + 1];
                *(float4*)(O + (size_t)gr * BN + tcol * TN + j * 2) =
                    make_float4(u0.f.x, u0.f.y, u1.f.x, u1.f.y);
            }
        }
    }
}

// ---------------- aggregation: out[n] = relu?(b + sum_e w_e * h[src_e]) ----------------
template<bool RELU>
__global__ __launch_bounds__(256)
void k_aggregate128(const float* __restrict__ h, const float* __restrict__ bias,
                    float* __restrict__ out) {
    int w    = (blockIdx.x * blockDim.x + threadIdx.x) >> 5;
    int lane = threadIdx.x & 31;
    if (w >= NNODES) return;
    int e = g_row[w], end = g_row[w + 1];
    float4 acc = make_float4(0.f, 0.f, 0.f, 0.f);
    for (; e + 4 <= end; e += 4) {
        int2 p0 = g_csr[e + 0];
        int2 p1 = g_csr[e + 1];
        int2 p2 = g_csr[e + 2];
        int2 p3 = g_csr[e + 3];
        float4 v0 = *(const float4*)(h + (size_t)p0.x * 128 + lane * 4);
        float4 v1 = *(const float4*)(h + (size_t)p1.x * 128 + lane * 4);
        float4 v2 = *(const float4*)(h + (size_t)p2.x * 128 + lane * 4);
        float4 v3 = *(const float4*)(h + (size_t)p3.x * 128 + lane * 4);
        float w0 = __int_as_float(p0.y), w1 = __int_as_float(p1.y);
        float w2 = __int_as_float(p2.y), w3 = __int_as_float(p3.y);
        acc.x = fmaf(w0, v0.x, acc.x); acc.y = fmaf(w0, v0.y, acc.y);
        acc.z = fmaf(w0, v0.z, acc.z); acc.w = fmaf(w0, v0.w, acc.w);
        acc.x = fmaf(w1, v1.x, acc.x); acc.y = fmaf(w1, v1.y, acc.y);
        acc.z = fmaf(w1, v1.z, acc.z); acc.w = fmaf(w1, v1.w, acc.w);
        acc.x = fmaf(w2, v2.x, acc.x); acc.y = fmaf(w2, v2.y, acc.y);
        acc.z = fmaf(w2, v2.z, acc.z); acc.w = fmaf(w2, v2.w, acc.w);
        acc.x = fmaf(w3, v3.x, acc.x); acc.y = fmaf(w3, v3.y, acc.y);
        acc.z = fmaf(w3, v3.z, acc.z); acc.w = fmaf(w3, v3.w, acc.w);
    }
    for (; e < end; e++) {
        int2 p = g_csr[e];
        float wt = __int_as_float(p.y);
        float4 v = *(const float4*)(h + (size_t)p.x * 128 + lane * 4);
        acc.x = fmaf(wt, v.x, acc.x); acc.y = fmaf(wt, v.y, acc.y);
        acc.z = fmaf(wt, v.z, acc.z); acc.w = fmaf(wt, v.w, acc.w);
    }
    float4 bb = *(const float4*)(bias + lane * 4);
    acc.x += bb.x; acc.y += bb.y; acc.z += bb.z; acc.w += bb.w;
    if (RELU) {
        acc.x = fmaxf(acc.x, 0.f); acc.y = fmaxf(acc.y, 0.f);
        acc.z = fmaxf(acc.z, 0.f); acc.w = fmaxf(acc.w, 0.f);
    }
    *(float4*)(out + (size_t)w * 128 + lane * 4) = acc;
}

template<bool RELU>
__global__ __launch_bounds__(256)
void k_aggregate64(const float* __restrict__ h, const float* __restrict__ bias,
                   float* __restrict__ out) {
    int w    = (blockIdx.x * blockDim.x + threadIdx.x) >> 5;
    int lane = threadIdx.x & 31;
    if (w >= NNODES) return;
    int e = g_row[w], end = g_row[w + 1];
    float2 acc = make_float2(0.f, 0.f);
    for (; e + 4 <= end; e += 4) {
        int2 p0 = g_csr[e + 0];
        int2 p1 = g_csr[e + 1];
        int2 p2 = g_csr[e + 2];
        int2 p3 = g_csr[e + 3];
        float2 v0 = *(const float2*)(h + (size_t)p0.x * 64 + lane * 2);
        float2 v1 = *(const float2*)(h + (size_t)p1.x * 64 + lane * 2);
        float2 v2 = *(const float2*)(h + (size_t)p2.x * 64 + lane * 2);
        float2 v3 = *(const float2*)(h + (size_t)p3.x * 64 + lane * 2);
        float w0 = __int_as_float(p0.y), w1 = __int_as_float(p1.y);
        float w2 = __int_as_float(p2.y), w3 = __int_as_float(p3.y);
        acc.x = fmaf(w0, v0.x, acc.x); acc.y = fmaf(w0, v0.y, acc.y);
        acc.x = fmaf(w1, v1.x, acc.x); acc.y = fmaf(w1, v1.y, acc.y);
        acc.x = fmaf(w2, v2.x, acc.x); acc.y = fmaf(w2, v2.y, acc.y);
        acc.x = fmaf(w3, v3.x, acc.x); acc.y = fmaf(w3, v3.y, acc.y);
    }
    for (; e < end; e++) {
        int2 p = g_csr[e];
        float wt = __int_as_float(p.y);
        float2 v = *(const float2*)(h + (size_t)p.x * 64 + lane * 2);
        acc.x = fmaf(wt, v.x, acc.x); acc.y = fmaf(wt, v.y, acc.y);
    }
    float2 bb = *(const float2*)(bias + lane * 2);
    acc.x += bb.x; acc.y += bb.y;
    if (RELU) { acc.x = fmaxf(acc.x, 0.f); acc.y = fmaxf(acc.y, 0.f); }
    *(float2*)(out + (size_t)w * 64 + lane * 2) = acc;
}

// ---------------- decode ----------------
__global__ __launch_bounds__(256)
void k_decode(const float* __restrict__ z, const int* __restrict__ eli,
              float* __restrict__ out) {
    int w    = (blockIdx.x * blockDim.x + threadIdx.x) >> 5;
    int lane = threadIdx.x & 31;
    if (w >= NLAB) return;
    int a = eli[w];
    int b = eli[NLAB + w];
    float2 za = *(const float2*)(z + (size_t)a * 64 + lane * 2);
    float2 zb = *(const float2*)(z + (size_t)b * 64 + lane * 2);
    float h0 = za.x * zb.x;
    float h1 = za.y * zb.y;
    float s  = h0 + h1;
    float q  = h0 * h0 + h1 * h1;
#pragma unroll
    for (int off = 16; off > 0; off >>= 1) {
        s += __shfl_xor_sync(0xFFFFFFFFu, s, off);
        q += __shfl_xor_sync(0xFFFFFFFFu, q, off);
    }
    float nrm = fmaxf(sqrtf(q), 1e-12f);
    float inv = 1.0f / nrm;
    *(float2*)(out + (size_t)w * 64 + lane * 2) = make_float2(h0 * inv, h1 * inv);
    if (lane == 0) out[(size_t)NLAB * 64 + w] = s;
}

// ---------------- launch ----------------
extern "C" void kernel_launch(void* const* d_in, const int* in_sizes, int n_in,
                              void* d_out, int out_size) {
    const float* x  = (const float*)d_in[0];
    const float* W1 = (const float*)d_in[1];
    const float* b1 = (const float*)d_in[2];
    const float* W2 = (const float*)d_in[3];
    const float* b2 = (const float*)d_in[4];
    const float* W3 = (const float*)d_in[5];
    const float* b3 = (const float*)d_in[6];
    const int*   ei  = (const int*)d_in[7];
    const int*   eli = (const int*)d_in[8];
    float* out = (float*)d_out;

    float* bufA = nullptr;
    float* bufB = nullptr;
    cudaGetSymbolAddress((void**)&bufA, g_bufA);
    cudaGetSymbolAddress((void**)&bufB, g_bufB);

    // One-time resource init. First kernel_launch call is the eager
    // correctness run (not under capture), so creation never happens
    // inside graph capture. No device memory is allocated here.
    static cudaStream_t s2 = nullptr;
    static cudaEvent_t ev0 = nullptr, ev1 = nullptr;
    if (s2 == nullptr) {
        cudaStreamCreateWithFlags(&s2, cudaStreamNonBlocking);
        cudaEventCreateWithFlags(&ev0, cudaEventDisableTiming);
        cudaEventCreateWithFlags(&ev1, cudaEventDisableTiming);
    }

    const int nscan = (NNODES + 1023) / 1024;   // 98
    const int gemm_grid = (NNODES + 127) / 128;       // 782
    const int agg_grid  = (NNODES * 32 + 255) / 256;  // 12500
    const int dec_grid  = (NLAB * 32 + 255) / 256;    // 25000

    // Fork: CSR build on s2, GEMM1 on default stream (independent work).
    cudaEventRecord(ev0, 0);
    cudaStreamWaitEvent(s2, ev0, 0);

    k_init<<<(NNODES + 255) / 256, 256, 0, s2>>>();                 // launch 0
    k_count<<<(NEDGES + 255) / 256, 256, 0, s2>>>(ei);              // launch 1
    k_dis<<<(NNODES + 255) / 256, 256, 0, s2>>>();                  // launch 2
    k_scan_blocks<<<nscan, 1024, 0, s2>>>();                        // launch 3
    k_scan_sums<<<1, 32, 0, s2>>>(nscan);                           // launch 4

    k_sgemm<128><<<gemm_grid, 256>>>(x, W1, bufB, NNODES);          // launch 5 (ncu -s 5 target)

    k_add_off<<<(NNODES + 255) / 256, 256, 0, s2>>>();              // launch 6
    k_fill_csr<<<(TOTE + 255) / 256, 256, 0, s2>>>(ei);             // launch 7
    cudaEventRecord(ev1, s2);
    cudaStreamWaitEvent(0, ev1, 0);

    // layer 1 aggregate, then layers 2/3 serial
    k_aggregate128<true><<<agg_grid, 256>>>(bufB, b1, bufA);
    k_sgemm<128><<<gemm_grid, 256>>>(bufA, W2, bufB, NNODES);
    k_aggregate128<true><<<agg_grid, 256>>>(bufB, b2, bufA);
    k_sgemm<64><<<gemm_grid, 256>>>(bufA, W3, bufB, NNODES);
    k_aggregate64<false><<<agg_grid, 256>>>(bufB, b3, bufA);
    k_decode<<<dec_grid, 256>>>(bufA, eli, out);
}

// round 6
// speedup vs baseline: 1.0427x; 1.0238x over previous
#include <cuda_runtime.h>
#include <cuda_bf16.h>
#include <math.h>
#include <stdint.h>

#define NNODES 100000
#define NEDGES 1600000
#define NLAB   200000
#define TOTE   (NEDGES + NNODES)

// ---------------- scratch (device globals; no allocation allowed) ----------------
__device__ int   g_deg[NNODES];
__device__ float g_dis[NNODES];
__device__ int   g_row[NNODES + 1];
__device__ int   g_cnt[NNODES];
__device__ int   g_bsum[128];
__device__ int2  g_csr[TOTE];            // packed (src, weight-bits)
__device__ float g_bufA[(size_t)NNODES * 128];
__device__ float g_bufB[(size_t)NNODES * 128];

// ---------------- warp-mma helpers (sm_80+ baseline ISA; no 'a' features) ----------------
__device__ __forceinline__ uint32_t smem_u32(const void* p) {
    uint32_t a;
    asm("{ .reg .u64 t; cvta.to.shared.u64 t, %1; cvt.u32.u64 %0, t; }" : "=r"(a) : "l"(p));
    return a;
}
__device__ __forceinline__ void ldsm_x4(uint32_t* r, uint32_t addr) {
    asm volatile("ldmatrix.sync.aligned.m8n8.x4.shared.b16 {%0,%1,%2,%3}, [%4];"
        : "=r"(r[0]), "=r"(r[1]), "=r"(r[2]), "=r"(r[3]) : "r"(addr));
}
__device__ __forceinline__ void mma_bf16(float* c, const uint32_t* a, const uint32_t* b) {
    asm volatile("mma.sync.aligned.m16n8k16.row.col.f32.bf16.bf16.f32 "
        "{%0,%1,%2,%3}, {%4,%5,%6,%7}, {%8,%9}, {%0,%1,%2,%3};"
        : "+f"(c[0]), "+f"(c[1]), "+f"(c[2]), "+f"(c[3])
        : "r"(a[0]), "r"(a[1]), "r"(a[2]), "r"(a[3]), "r"(b[0]), "r"(b[1]));
}

// ---------------- CSR build ----------------
__global__ void k_init(void) {
    int i = blockIdx.x * blockDim.x + threadIdx.x;
    if (i < NNODES) { g_deg[i] = 1; g_cnt[i] = 0; }
}
__global__ void k_count(const int* __restrict__ ei) {
    int e = blockIdx.x * blockDim.x + threadIdx.x;
    if (e < NEDGES) atomicAdd(&g_deg[ei[NEDGES + e]], 1);
}
__global__ void k_dis(void) {
    int i = blockIdx.x * blockDim.x + threadIdx.x;
    if (i < NNODES) g_dis[i] = rsqrtf((float)g_deg[i]);
}
__global__ void k_scan_blocks(void) {
    __shared__ int sh[1024];
    int i = blockIdx.x * 1024 + threadIdx.x;
    int v = (i < NNODES) ? g_deg[i] : 0;
    sh[threadIdx.x] = v;
    __syncthreads();
    for (int off = 1; off < 1024; off <<= 1) {
        int t = (threadIdx.x >= off) ? sh[threadIdx.x - off] : 0;
        __syncthreads();
        sh[threadIdx.x] += t;
        __syncthreads();
    }
    if (i < NNODES) g_row[i] = sh[threadIdx.x] - v;
    if (threadIdx.x == 1023) g_bsum[blockIdx.x] = sh[1023];
}
__global__ void k_scan_sums2(int nblocks) {     // parallel 128-wide scan
    __shared__ int sh[128];
    int t = threadIdx.x;
    int v = (t < nblocks) ? g_bsum[t] : 0;
    sh[t] = v;
    __syncthreads();
    for (int off = 1; off < 128; off <<= 1) {
        int u = (t >= off) ? sh[t - off] : 0;
        __syncthreads();
        sh[t] += u;
        __syncthreads();
    }
    if (t < nblocks) g_bsum[t] = sh[t] - v;     // exclusive
}
__global__ void k_add_off(void) {
    int i = blockIdx.x * blockDim.x + threadIdx.x;
    if (i < NNODES) g_row[i] += g_bsum[i >> 10];
    if (i == 0) g_row[NNODES] = TOTE;
}
__global__ void k_fill_csr(const int* __restrict__ ei) {
    int idx = blockIdx.x * blockDim.x + threadIdx.x;
    if (idx >= TOTE) return;
    int s, d;
    if (idx < NEDGES) { s = ei[idx]; d = ei[NEDGES + idx]; }
    else              { s = d = idx - NEDGES; }
    int pos = g_row[d] + atomicAdd(&g_cnt[d], 1);
    float w = g_dis[s] * g_dis[d];
    g_csr[pos] = make_int2(s, __float_as_int(w));
}

// ---------------- mma.sync bf16 GEMM: O[M,BN] = X[M,128] @ W[128,BN] ----------------
// 2-way bf16 split: O = Ah@Bh + Ah@Bl + Al@Bh (residual ~2^-16).
// A staged row-major [128 x 128], B staged n-major [BN x 128], stride 136 bf16
// (272B rows -> conflict-free ldmatrix). Whole K resident; 8 k-steps of 16.
template<int BN>
__global__ __launch_bounds__(256, 1)
void k_mma_gemm(const float* __restrict__ X, const float* __restrict__ W,
                float* __restrict__ O, int M) {
    constexpr int LDA = 136;                 // padded stride in bf16 elems
    constexpr int ASZ = 128 * LDA;
    constexpr int BSZ = BN * LDA;
    // warp layout: BN=128 -> 2x4 warps, warp tile 64x32; BN=64 -> 4x2, tile 32x32
    constexpr int WM = (BN == 128) ? 2 : 4;
    constexpr int MT = 128 / WM / 16;        // m16 tiles per warp: 4 or 2
    constexpr int NT = 4;                    // n8 tiles per warp (32 cols)

    extern __shared__ __align__(16) __nv_bfloat16 smx[];
    __nv_bfloat16* Ah = smx;
    __nv_bfloat16* Al = Ah + ASZ;
    __nv_bfloat16* Bh = Al + ASZ;
    __nv_bfloat16* Bl = Bh + BSZ;

    int tid = threadIdx.x, wid = tid >> 5, lane = tid & 31;
    int brow = blockIdx.x * 128;

    // ---- stage A: fp32 -> bf16 hi/lo ----
    for (int idx = tid; idx < 128 * 32; idx += 256) {
        int r = idx >> 5, c4 = (idx & 31) * 4;
        float4 v = make_float4(0.f, 0.f, 0.f, 0.f);
        int gr = brow + r;
        if (gr < M) v = *(const float4*)(X + (size_t)gr * 128 + c4);
        float f[4] = {v.x, v.y, v.z, v.w};
        __nv_bfloat16 h[4], l[4];
#pragma unroll
        for (int j = 0; j < 4; j++) {
            h[j] = __float2bfloat16_rn(f[j]);
            l[j] = __float2bfloat16_rn(f[j] - __bfloat162float(h[j]));
        }
        int o = r * LDA + c4;
        *(__nv_bfloat162*)(Ah + o)     = __nv_bfloat162(h[0], h[1]);
        *(__nv_bfloat162*)(Ah + o + 2) = __nv_bfloat162(h[2], h[3]);
        *(__nv_bfloat162*)(Al + o)     = __nv_bfloat162(l[0], l[1]);
        *(__nv_bfloat162*)(Al + o + 2) = __nv_bfloat162(l[2], l[3]);
    }
    // ---- stage B transposed: Bt[n][k] (coalesced reads, 8B smem stores) ----
    for (int idx = tid; idx < 32 * BN; idx += 256) {
        int n  = idx % BN;
        int k0 = (idx / BN) * 4;
        float f[4];
#pragma unroll
        for (int j = 0; j < 4; j++) f[j] = W[(size_t)(k0 + j) * BN + n];
        __nv_bfloat16 h[4], l[4];
#pragma unroll
        for (int j = 0; j < 4; j++) {
            h[j] = __float2bfloat16_rn(f[j]);
            l[j] = __float2bfloat16_rn(f[j] - __bfloat162float(h[j]));
        }
        int o = n * LDA + k0;
        *(__nv_bfloat162*)(Bh + o)     = __nv_bfloat162(h[0], h[1]);
        *(__nv_bfloat162*)(Bh + o + 2) = __nv_bfloat162(h[2], h[3]);
        *(__nv_bfloat162*)(Bl + o)     = __nv_bfloat162(l[0], l[1]);
        *(__nv_bfloat162*)(Bl + o + 2) = __nv_bfloat162(l[2], l[3]);
    }
    __syncthreads();

    int wm = wid % WM, wn = wid / WM;
    int rows0 = wm * (MT * 16);
    int col0  = wn * 32;

    // per-lane ldmatrix address components
    int a_r = rows0 + (lane & 15);
    int a_c = (lane & 16) >> 1;                       // 0 or 8
    int b_r = col0 + (lane & 7) + ((lane & 16) >> 1); // n row
    int b_c = (lane & 8);                             // 0 or 8 (k offset)
    uint32_t ah_base = smem_u32(Ah) + (uint32_t)(a_r * LDA + a_c) * 2;
    uint32_t al_base = smem_u32(Al) + (uint32_t)(a_r * LDA + a_c) * 2;
    uint32_t bh_base = smem_u32(Bh) + (uint32_t)(b_r * LDA + b_c) * 2;
    uint32_t bl_base = smem_u32(Bl) + (uint32_t)(b_r * LDA + b_c) * 2;

    float acc[MT][NT][4];
#pragma unroll
    for (int m = 0; m < MT; m++)
#pragma unroll
        for (int n = 0; n < NT; n++)
#pragma unroll
            for (int q = 0; q < 4; q++) acc[m][n][q] = 0.f;

#pragma unroll
    for (int ks = 0; ks < 8; ks++) {
        uint32_t koff = (uint32_t)(ks * 16) * 2;
        uint32_t ah[MT][4], al[MT][4], bh[2][4], bl[2][4];
#pragma unroll
        for (int m = 0; m < MT; m++) {
            uint32_t moff = (uint32_t)(m * 16 * LDA) * 2;
            ldsm_x4(ah[m], ah_base + moff + koff);
            ldsm_x4(al[m], al_base + moff + koff);
        }
#pragma unroll
        for (int p = 0; p < 2; p++) {
            uint32_t poff = (uint32_t)(p * 16 * LDA) * 2;
            ldsm_x4(bh[p], bh_base + poff + koff);
            ldsm_x4(bl[p], bl_base + poff + koff);
        }
#pragma unroll
        for (int m = 0; m < MT; m++) {
#pragma unroll
            for (int p = 0; p < 2; p++) {
                mma_bf16(acc[m][2 * p],     ah[m], &bh[p][0]);
                mma_bf16(acc[m][2 * p],     ah[m], &bl[p][0]);
                mma_bf16(acc[m][2 * p],     al[m], &bh[p][0]);
                mma_bf16(acc[m][2 * p + 1], ah[m], &bh[p][2]);
                mma_bf16(acc[m][2 * p + 1], ah[m], &bl[p][2]);
                mma_bf16(acc[m][2 * p + 1], al[m], &bh[p][2]);
            }
        }
    }

    // ---- epilogue: C frag -> gmem (float2 per row half) ----
    int gid  = lane >> 2;       // 0..7
    int quad = lane & 3;        // 0..3
#pragma unroll
    for (int m = 0; m < MT; m++) {
        int r0 = brow + rows0 + m * 16 + gid;
#pragma unroll
        for (int n = 0; n < NT; n++) {
            int c = col0 + n * 8 + quad * 2;
            if (r0 < M)
                *(float2*)(O + (size_t)r0 * BN + c) = make_float2(acc[m][n][0], acc[m][n][1]);
            if (r0 + 8 < M)
                *(float2*)(O + (size_t)(r0 + 8) * BN + c) = make_float2(acc[m][n][2], acc[m][n][3]);
        }
    }
}

// ---------------- aggregation: out[n] = relu?(b + sum_e w_e * h[src_e]) ----------------
template<bool RELU>
__global__ __launch_bounds__(256)
void k_aggregate128(const float* __restrict__ h, const float* __restrict__ bias,
                    float* __restrict__ out) {
    int w    = (blockIdx.x * blockDim.x + threadIdx.x) >> 5;
    int lane = threadIdx.x & 31;
    if (w >= NNODES) return;
    int e = g_row[w], end = g_row[w + 1];
    float4 acc = make_float4(0.f, 0.f, 0.f, 0.f);
    for (; e + 4 <= end; e += 4) {
        int2 p0 = g_csr[e + 0];
        int2 p1 = g_csr[e + 1];
        int2 p2 = g_csr[e + 2];
        int2 p3 = g_csr[e + 3];
        float4 v0 = *(const float4*)(h + (size_t)p0.x * 128 + lane * 4);
        float4 v1 = *(const float4*)(h + (size_t)p1.x * 128 + lane * 4);
        float4 v2 = *(const float4*)(h + (size_t)p2.x * 128 + lane * 4);
        float4 v3 = *(const float4*)(h + (size_t)p3.x * 128 + lane * 4);
        float w0 = __int_as_float(p0.y), w1 = __int_as_float(p1.y);
        float w2 = __int_as_float(p2.y), w3 = __int_as_float(p3.y);
        acc.x = fmaf(w0, v0.x, acc.x); acc.y = fmaf(w0, v0.y, acc.y);
        acc.z = fmaf(w0, v0.z, acc.z); acc.w = fmaf(w0, v0.w, acc.w);
        acc.x = fmaf(w1, v1.x, acc.x); acc.y = fmaf(w1, v1.y, acc.y);
        acc.z = fmaf(w1, v1.z, acc.z); acc.w = fmaf(w1, v1.w, acc.w);
        acc.x = fmaf(w2, v2.x, acc.x); acc.y = fmaf(w2, v2.y, acc.y);
        acc.z = fmaf(w2, v2.z, acc.z); acc.w = fmaf(w2, v2.w, acc.w);
        acc.x = fmaf(w3, v3.x, acc.x); acc.y = fmaf(w3, v3.y, acc.y);
        acc.z = fmaf(w3, v3.z, acc.z); acc.w = fmaf(w3, v3.w, acc.w);
    }
    for (; e < end; e++) {
        int2 p = g_csr[e];
        float wt = __int_as_float(p.y);
        float4 v = *(const float4*)(h + (size_t)p.x * 128 + lane * 4);
        acc.x = fmaf(wt, v.x, acc.x); acc.y = fmaf(wt, v.y, acc.y);
        acc.z = fmaf(wt, v.z, acc.z); acc.w = fmaf(wt, v.w, acc.w);
    }
    float4 bb = *(const float4*)(bias + lane * 4);
    acc.x += bb.x; acc.y += bb.y; acc.z += bb.z; acc.w += bb.w;
    if (RELU) {
        acc.x = fmaxf(acc.x, 0.f); acc.y = fmaxf(acc.y, 0.f);
        acc.z = fmaxf(acc.z, 0.f); acc.w = fmaxf(acc.w, 0.f);
    }
    *(float4*)(out + (size_t)w * 128 + lane * 4) = acc;
}

template<bool RELU>
__global__ __launch_bounds__(256)
void k_aggregate64(const float* __restrict__ h, const float* __restrict__ bias,
                   float* __restrict__ out) {
    int w    = (blockIdx.x * blockDim.x + threadIdx.x) >> 5;
    int lane = threadIdx.x & 31;
    if (w >= NNODES) return;
    int e = g_row[w], end = g_row[w + 1];
    float2 acc = make_float2(0.f, 0.f);
    for (; e + 4 <= end; e += 4) {
        int2 p0 = g_csr[e + 0];
        int2 p1 = g_csr[e + 1];
        int2 p2 = g_csr[e + 2];
        int2 p3 = g_csr[e + 3];
        float2 v0 = *(const float2*)(h + (size_t)p0.x * 64 + lane * 2);
        float2 v1 = *(const float2*)(h + (size_t)p1.x * 64 + lane * 2);
        float2 v2 = *(const float2*)(h + (size_t)p2.x * 64 + lane * 2);
        float2 v3 = *(const float2*)(h + (size_t)p3.x * 64 + lane * 2);
        float w0 = __int_as_float(p0.y), w1 = __int_as_float(p1.y);
        float w2 = __int_as_float(p2.y), w3 = __int_as_float(p3.y);
        acc.x = fmaf(w0, v0.x, acc.x); acc.y = fmaf(w0, v0.y, acc.y);
        acc.x = fmaf(w1, v1.x, acc.x); acc.y = fmaf(w1, v1.y, acc.y);
        acc.x = fmaf(w2, v2.x, acc.x); acc.y = fmaf(w2, v2.y, acc.y);
        acc.x = fmaf(w3, v3.x, acc.x); acc.y = fmaf(w3, v3.y, acc.y);
    }
    for (; e < end; e++) {
        int2 p = g_csr[e];
        float wt = __int_as_float(p.y);
        float2 v = *(const float2*)(h + (size_t)p.x * 64 + lane * 2);
        acc.x = fmaf(wt, v.x, acc.x); acc.y = fmaf(wt, v.y, acc.y);
    }
    float2 bb = *(const float2*)(bias + lane * 2);
    acc.x += bb.x; acc.y += bb.y;
    if (RELU) { acc.x = fmaxf(acc.x, 0.f); acc.y = fmaxf(acc.y, 0.f); }
    *(float2*)(out + (size_t)w * 64 + lane * 2) = acc;
}

// ---------------- decode ----------------
__global__ __launch_bounds__(256)
void k_decode(const float* __restrict__ z, const int* __restrict__ eli,
              float* __restrict__ out) {
    int w    = (blockIdx.x * blockDim.x + threadIdx.x) >> 5;
    int lane = threadIdx.x & 31;
    if (w >= NLAB) return;
    int a = eli[w];
    int b = eli[NLAB + w];
    float2 za = *(const float2*)(z + (size_t)a * 64 + lane * 2);
    float2 zb = *(const float2*)(z + (size_t)b * 64 + lane * 2);
    float h0 = za.x * zb.x;
    float h1 = za.y * zb.y;
    float s  = h0 + h1;
    float q  = h0 * h0 + h1 * h1;
#pragma unroll
    for (int off = 16; off > 0; off >>= 1) {
        s += __shfl_xor_sync(0xFFFFFFFFu, s, off);
        q += __shfl_xor_sync(0xFFFFFFFFu, q, off);
    }
    float nrm = fmaxf(sqrtf(q), 1e-12f);
    float inv = 1.0f / nrm;
    *(float2*)(out + (size_t)w * 64 + lane * 2) = make_float2(h0 * inv, h1 * inv);
    if (lane == 0) out[(size_t)NLAB * 64 + w] = s;
}

// ---------------- launch ----------------
extern "C" void kernel_launch(void* const* d_in, const int* in_sizes, int n_in,
                              void* d_out, int out_size) {
    const float* x  = (const float*)d_in[0];
    const float* W1 = (const float*)d_in[1];
    const float* b1 = (const float*)d_in[2];
    const float* W2 = (const float*)d_in[3];
    const float* b2 = (const float*)d_in[4];
    const float* W3 = (const float*)d_in[5];
    const float* b3 = (const float*)d_in[6];
    const int*   ei  = (const int*)d_in[7];
    const int*   eli = (const int*)d_in[8];
    float* out = (float*)d_out;

    float* bufA = nullptr;
    float* bufB = nullptr;
    cudaGetSymbolAddress((void**)&bufA, g_bufA);
    cudaGetSymbolAddress((void**)&bufB, g_bufB);

    const int SMEM128 = (2 * 128 * 136 + 2 * 128 * 136) * 2;   // 139264 B
    const int SMEM64  = (2 * 128 * 136 + 2 * 64 * 136) * 2;    // 104448 B

    // One-time init: first call is the eager correctness run (not under
    // capture). Stream/event creation and func attributes happen here only.
    static cudaStream_t s2 = nullptr;
    static cudaEvent_t ev0 = nullptr, ev1 = nullptr;
    if (s2 == nullptr) {
        cudaStreamCreateWithFlags(&s2, cudaStreamNonBlocking);
        cudaEventCreateWithFlags(&ev0, cudaEventDisableTiming);
        cudaEventCreateWithFlags(&ev1, cudaEventDisableTiming);
        cudaFuncSetAttribute(k_mma_gemm<128>, cudaFuncAttributeMaxDynamicSharedMemorySize, SMEM128);
        cudaFuncSetAttribute(k_mma_gemm<64>,  cudaFuncAttributeMaxDynamicSharedMemorySize, SMEM64);
    }

    const int nscan = (NNODES + 1023) / 1024;           // 98
    const int gemm_grid = (NNODES + 127) / 128;         // 782
    const int agg_grid  = (NNODES * 32 + 255) / 256;    // 12500
    const int dec_grid  = (NLAB * 32 + 255) / 256;      // 25000

    // Fork: CSR build on s2, GEMM1 on default stream (independent work).
    cudaEventRecord(ev0, 0);
    cudaStreamWaitEvent(s2, ev0, 0);

    k_init<<<(NNODES + 255) / 256, 256, 0, s2>>>();
    k_count<<<(NEDGES + 255) / 256, 256, 0, s2>>>(ei);
    k_dis<<<(NNODES + 255) / 256, 256, 0, s2>>>();
    k_scan_blocks<<<nscan, 1024, 0, s2>>>();
    k_scan_sums2<<<1, 128, 0, s2>>>(nscan);

    k_mma_gemm<128><<<gemm_grid, 256, SMEM128>>>(x, W1, bufB, NNODES);   // launch 5 (ncu -s 5)

    k_add_off<<<(NNODES + 255) / 256, 256, 0, s2>>>();
    k_fill_csr<<<(TOTE + 255) / 256, 256, 0, s2>>>(ei);
    cudaEventRecord(ev1, s2);
    cudaStreamWaitEvent(0, ev1, 0);

    k_aggregate128<true><<<agg_grid, 256>>>(bufB, b1, bufA);
    k_mma_gemm<128><<<gemm_grid, 256, SMEM128>>>(bufA, W2, bufB, NNODES);
    k_aggregate128<true><<<agg_grid, 256>>>(bufB, b2, bufA);
    k_mma_gemm<64><<<gemm_grid, 256, SMEM64>>>(bufA, W3, bufB, NNODES);
    k_aggregate64<false><<<agg_grid, 256>>>(bufB, b3, bufA);
    k_decode<<<dec_grid, 256>>>(bufA, eli, out);
}

// round 8
// speedup vs baseline: 1.1580x; 1.1106x over previous
#include <cuda_runtime.h>
#include <cuda_bf16.h>
#include <math.h>
#include <stdint.h>

#define NNODES 100000
#define NEDGES 1600000
#define NLAB   200000
#define TOTE   (NEDGES + NNODES)

// ---------------- scratch (device globals; no allocation allowed) ----------------
__device__ int   g_deg[NNODES];
__device__ float g_dis[NNODES];
__device__ int   g_row[NNODES + 1];
__device__ int   g_cnt[NNODES];
__device__ int   g_bsum[128];
__device__ int2  g_csr[TOTE];            // packed (src, weight-bits)
__device__ float g_bufA[(size_t)NNODES * 128];
__device__ float g_bufB[(size_t)NNODES * 128];

// ---------------- warp-mma helpers (sm_80+ baseline ISA; no 'a' features) ----------------
__device__ __forceinline__ uint32_t smem_u32(const void* p) {
    uint32_t a;
    asm("{ .reg .u64 t; cvta.to.shared.u64 t, %1; cvt.u32.u64 %0, t; }" : "=r"(a) : "l"(p));
    return a;
}
__device__ __forceinline__ void ldsm_x4(uint32_t* r, uint32_t addr) {
    asm volatile("ldmatrix.sync.aligned.m8n8.x4.shared.b16 {%0,%1,%2,%3}, [%4];"
        : "=r"(r[0]), "=r"(r[1]), "=r"(r[2]), "=r"(r[3]) : "r"(addr));
}
__device__ __forceinline__ void mma_bf16(float* c, const uint32_t* a, const uint32_t* b) {
    asm volatile("mma.sync.aligned.m16n8k16.row.col.f32.bf16.bf16.f32 "
        "{%0,%1,%2,%3}, {%4,%5,%6,%7}, {%8,%9}, {%0,%1,%2,%3};"
        : "+f"(c[0]), "+f"(c[1]), "+f"(c[2]), "+f"(c[3])
        : "r"(a[0]), "r"(a[1]), "r"(a[2]), "r"(a[3]), "r"(b[0]), "r"(b[1]));
}

// ---------------- CSR build ----------------
__global__ void k_init(void) {
    int i = blockIdx.x * blockDim.x + threadIdx.x;
    if (i < NNODES) { g_deg[i] = 1; g_cnt[i] = 0; }
}
__global__ void k_count(const int* __restrict__ ei) {
    int e = blockIdx.x * blockDim.x + threadIdx.x;
    if (e < NEDGES) atomicAdd(&g_deg[ei[NEDGES + e]], 1);
}
__global__ void k_dis(void) {
    int i = blockIdx.x * blockDim.x + threadIdx.x;
    if (i < NNODES) g_dis[i] = rsqrtf((float)g_deg[i]);
}
__global__ void k_scan_blocks(void) {
    __shared__ int sh[1024];
    int i = blockIdx.x * 1024 + threadIdx.x;
    int v = (i < NNODES) ? g_deg[i] : 0;
    sh[threadIdx.x] = v;
    __syncthreads();
    for (int off = 1; off < 1024; off <<= 1) {
        int t = (threadIdx.x >= off) ? sh[threadIdx.x - off] : 0;
        __syncthreads();
        sh[threadIdx.x] += t;
        __syncthreads();
    }
    if (i < NNODES) g_row[i] = sh[threadIdx.x] - v;
    if (threadIdx.x == 1023) g_bsum[blockIdx.x] = sh[1023];
}
__global__ void k_scan_sums2(int nblocks) {     // parallel 128-wide scan
    __shared__ int sh[128];
    int t = threadIdx.x;
    int v = (t < nblocks) ? g_bsum[t] : 0;
    sh[t] = v;
    __syncthreads();
    for (int off = 1; off < 128; off <<= 1) {
        int u = (t >= off) ? sh[t - off] : 0;
        __syncthreads();
        sh[t] += u;
        __syncthreads();
    }
    if (t < nblocks) g_bsum[t] = sh[t] - v;     // exclusive
}
__global__ void k_add_off(void) {
    int i = blockIdx.x * blockDim.x + threadIdx.x;
    if (i < NNODES) g_row[i] += g_bsum[i >> 10];
    if (i == 0) g_row[NNODES] = TOTE;
}
__global__ void k_fill_csr(const int* __restrict__ ei) {
    int idx = blockIdx.x * blockDim.x + threadIdx.x;
    if (idx >= TOTE) return;
    int s, d;
    if (idx < NEDGES) { s = ei[idx]; d = ei[NEDGES + idx]; }
    else              { s = d = idx - NEDGES; }
    int pos = g_row[d] + atomicAdd(&g_cnt[d], 1);
    float w = g_dis[s] * g_dis[d];
    g_csr[pos] = make_int2(s, __float_as_int(w));
}

// ---------------- mma.sync bf16 GEMM: O[M,BN] = X[M,128] @ W[128,BN] ----------------
// 2-way bf16 split: O = Ah@Bh + Ah@Bl + Al@Bh (residual ~2^-16).
// K staged in two 64-wide chunks -> smem 72KB -> 2 CTAs/SM (staging overlaps
// the co-resident CTA's HMMA). LDA=72 (144B rows, bank stride ≡4 mod 32 ->
// conflict-free ldmatrix, same class as validated LDA=136).
template<int BN>
__global__ __launch_bounds__(256, 2)
void k_mma_gemm(const float* __restrict__ X, const float* __restrict__ W,
                float* __restrict__ O, int M) {
    constexpr int LDA = 72;                  // padded stride in bf16 elems (chunk K=64)
    constexpr int ASZ = 128 * LDA;
    constexpr int BSZ = BN * LDA;
    constexpr int WM = (BN == 128) ? 2 : 4;  // warps along M
    constexpr int MT = 128 / WM / 16;        // m16 tiles per warp: 4 or 2
    constexpr int NT = 4;                    // n8 tiles per warp (32 cols)

    extern __shared__ __align__(16) __nv_bfloat16 smx[];
    __nv_bfloat16* Ah = smx;
    __nv_bfloat16* Al = Ah + ASZ;
    __nv_bfloat16* Bh = Al + ASZ;
    __nv_bfloat16* Bl = Bh + BSZ;

    int tid = threadIdx.x, wid = tid >> 5, lane = tid & 31;
    int brow = blockIdx.x * 128;

    int wm = wid % WM, wn = wid / WM;
    int rows0 = wm * (MT * 16);
    int col0  = wn * 32;

    // per-lane ldmatrix address components (within a 64-wide K chunk)
    int a_r = rows0 + (lane & 15);
    int a_c = (lane & 16) >> 1;                       // 0 or 8
    int b_r = col0 + (lane & 7) + ((lane & 16) >> 1); // n row
    int b_c = (lane & 8);                             // 0 or 8 (k offset)
    uint32_t ah_base = smem_u32(Ah) + (uint32_t)(a_r * LDA + a_c) * 2;
    uint32_t al_base = smem_u32(Al) + (uint32_t)(a_r * LDA + a_c) * 2;
    uint32_t bh_base = smem_u32(Bh) + (uint32_t)(b_r * LDA + b_c) * 2;
    uint32_t bl_base = smem_u32(Bl) + (uint32_t)(b_r * LDA + b_c) * 2;

    float acc[MT][NT][4];
#pragma unroll
    for (int m = 0; m < MT; m++)
#pragma unroll
        for (int n = 0; n < NT; n++)
#pragma unroll
            for (int q = 0; q < 4; q++) acc[m][n][q] = 0.f;

    for (int kc = 0; kc < 128; kc += 64) {
        // ---- stage A chunk: 128 rows x 64 cols, fp32 -> bf16 hi/lo ----
        for (int idx = tid; idx < 128 * 16; idx += 256) {
            int r = idx >> 4, c4 = (idx & 15) * 4;
            float4 v = make_float4(0.f, 0.f, 0.f, 0.f);
            int gr = brow + r;
            if (gr < M) v = *(const float4*)(X + (size_t)gr * 128 + kc + c4);
            float f[4] = {v.x, v.y, v.z, v.w};
            __nv_bfloat16 h[4], l[4];
#pragma unroll
            for (int j = 0; j < 4; j++) {
                h[j] = __float2bfloat16_rn(f[j]);
                l[j] = __float2bfloat16_rn(f[j] - __bfloat162float(h[j]));
            }
            int o = r * LDA + c4;
            *(__nv_bfloat162*)(Ah + o)     = __nv_bfloat162(h[0], h[1]);
            *(__nv_bfloat162*)(Ah + o + 2) = __nv_bfloat162(h[2], h[3]);
            *(__nv_bfloat162*)(Al + o)     = __nv_bfloat162(l[0], l[1]);
            *(__nv_bfloat162*)(Al + o + 2) = __nv_bfloat162(l[2], l[3]);
        }
        // ---- stage B chunk transposed: Bt[n][k-kc] ----
        for (int idx = tid; idx < 16 * BN; idx += 256) {
            int n  = idx % BN;
            int k0 = (idx / BN) * 4;
            float f[4];
#pragma unroll
            for (int j = 0; j < 4; j++) f[j] = W[(size_t)(kc + k0 + j) * BN + n];
            __nv_bfloat16 h[4], l[4];
#pragma unroll
            for (int j = 0; j < 4; j++) {
                h[j] = __float2bfloat16_rn(f[j]);
                l[j] = __float2bfloat16_rn(f[j] - __bfloat162float(h[j]));
            }
            int o = n * LDA + k0;
            *(__nv_bfloat162*)(Bh + o)     = __nv_bfloat162(h[0], h[1]);
            *(__nv_bfloat162*)(Bh + o + 2) = __nv_bfloat162(h[2], h[3]);
            *(__nv_bfloat162*)(Bl + o)     = __nv_bfloat162(l[0], l[1]);
            *(__nv_bfloat162*)(Bl + o + 2) = __nv_bfloat162(l[2], l[3]);
        }
        __syncthreads();

#pragma unroll
        for (int ks = 0; ks < 4; ks++) {
            uint32_t koff = (uint32_t)(ks * 16) * 2;
            uint32_t ah[MT][4], al[MT][4], bh[2][4], bl[2][4];
#pragma unroll
            for (int m = 0; m < MT; m++) {
                uint32_t moff = (uint32_t)(m * 16 * LDA) * 2;
                ldsm_x4(ah[m], ah_base + moff + koff);
                ldsm_x4(al[m], al_base + moff + koff);
            }
#pragma unroll
            for (int p = 0; p < 2; p++) {
                uint32_t poff = (uint32_t)(p * 16 * LDA) * 2;
                ldsm_x4(bh[p], bh_base + poff + koff);
                ldsm_x4(bl[p], bl_base + poff + koff);
            }
#pragma unroll
            for (int m = 0; m < MT; m++) {
#pragma unroll
                for (int p = 0; p < 2; p++) {
                    mma_bf16(acc[m][2 * p],     ah[m], &bh[p][0]);
                    mma_bf16(acc[m][2 * p],     ah[m], &bl[p][0]);
                    mma_bf16(acc[m][2 * p],     al[m], &bh[p][0]);
                    mma_bf16(acc[m][2 * p + 1], ah[m], &bh[p][2]);
                    mma_bf16(acc[m][2 * p + 1], ah[m], &bl[p][2]);
                    mma_bf16(acc[m][2 * p + 1], al[m], &bh[p][2]);
                }
            }
        }
        __syncthreads();
    }

    // ---- epilogue: C frag -> gmem (float2 per row half) ----
    int gid  = lane >> 2;       // 0..7
    int quad = lane & 3;        // 0..3
#pragma unroll
    for (int m = 0; m < MT; m++) {
        int r0 = brow + rows0 + m * 16 + gid;
#pragma unroll
        for (int n = 0; n < NT; n++) {
            int c = col0 + n * 8 + quad * 2;
            if (r0 < M)
                *(float2*)(O + (size_t)r0 * BN + c) = make_float2(acc[m][n][0], acc[m][n][1]);
            if (r0 + 8 < M)
                *(float2*)(O + (size_t)(r0 + 8) * BN + c) = make_float2(acc[m][n][2], acc[m][n][3]);
        }
    }
}

// ---------------- aggregation (128-wide): 2 warps per node, 256B half-rows ----------------
template<bool RELU>
__global__ __launch_bounds__(256)
void k_aggregate128(const float* __restrict__ h, const float* __restrict__ bias,
                    float* __restrict__ out) {
    int gw   = (blockIdx.x * blockDim.x + threadIdx.x) >> 5;
    int lane = threadIdx.x & 31;
    int node = gw >> 1;
    int half = gw & 1;
    if (node >= NNODES) return;
    const float* hh = h + half * 64;
    int e = g_row[node], end = g_row[node + 1];
    float2 acc = make_float2(0.f, 0.f);
    for (; e + 4 <= end; e += 4) {
        int2 p0 = g_csr[e + 0];
        int2 p1 = g_csr[e + 1];
        int2 p2 = g_csr[e + 2];
        int2 p3 = g_csr[e + 3];
        float2 v0 = *(const float2*)(hh + (size_t)p0.x * 128 + lane * 2);
        float2 v1 = *(const float2*)(hh + (size_t)p1.x * 128 + lane * 2);
        float2 v2 = *(const float2*)(hh + (size_t)p2.x * 128 + lane * 2);
        float2 v3 = *(const float2*)(hh + (size_t)p3.x * 128 + lane * 2);
        float w0 = __int_as_float(p0.y), w1 = __int_as_float(p1.y);
        float w2 = __int_as_float(p2.y), w3 = __int_as_float(p3.y);
        acc.x = fmaf(w0, v0.x, acc.x); acc.y = fmaf(w0, v0.y, acc.y);
        acc.x = fmaf(w1, v1.x, acc.x); acc.y = fmaf(w1, v1.y, acc.y);
        acc.x = fmaf(w2, v2.x, acc.x); acc.y = fmaf(w2, v2.y, acc.y);
        acc.x = fmaf(w3, v3.x, acc.x); acc.y = fmaf(w3, v3.y, acc.y);
    }
    for (; e < end; e++) {
        int2 p = g_csr[e];
        float wt = __int_as_float(p.y);
        float2 v = *(const float2*)(hh + (size_t)p.x * 128 + lane * 2);
        acc.x = fmaf(wt, v.x, acc.x); acc.y = fmaf(wt, v.y, acc.y);
    }
    float2 bb = *(const float2*)(bias + half * 64 + lane * 2);
    acc.x += bb.x; acc.y += bb.y;
    if (RELU) { acc.x = fmaxf(acc.x, 0.f); acc.y = fmaxf(acc.y, 0.f); }
    *(float2*)(out + (size_t)node * 128 + half * 64 + lane * 2) = acc;
}

template<bool RELU>
__global__ __launch_bounds__(256)
void k_aggregate64(const float* __restrict__ h, const float* __restrict__ bias,
                   float* __restrict__ out) {
    int w    = (blockIdx.x * blockDim.x + threadIdx.x) >> 5;
    int lane = threadIdx.x & 31;
    if (w >= NNODES) return;
    int e = g_row[w], end = g_row[w + 1];
    float2 acc = make_float2(0.f, 0.f);
    for (; e + 4 <= end; e += 4) {
        int2 p0 = g_csr[e + 0];
        int2 p1 = g_csr[e + 1];
        int2 p2 = g_csr[e + 2];
        int2 p3 = g_csr[e + 3];
        float2 v0 = *(const float2*)(h + (size_t)p0.x * 64 + lane * 2);
        float2 v1 = *(const float2*)(h + (size_t)p1.x * 64 + lane * 2);
        float2 v2 = *(const float2*)(h + (size_t)p2.x * 64 + lane * 2);
        float2 v3 = *(const float2*)(h + (size_t)p3.x * 64 + lane * 2);
        float w0 = __int_as_float(p0.y), w1 = __int_as_float(p1.y);
        float w2 = __int_as_float(p2.y), w3 = __int_as_float(p3.y);
        acc.x = fmaf(w0, v0.x, acc.x); acc.y = fmaf(w0, v0.y, acc.y);
        acc.x = fmaf(w1, v1.x, acc.x); acc.y = fmaf(w1, v1.y, acc.y);
        acc.x = fmaf(w2, v2.x, acc.x); acc.y = fmaf(w2, v2.y, acc.y);
        acc.x = fmaf(w3, v3.x, acc.x); acc.y = fmaf(w3, v3.y, acc.y);
    }
    for (; e < end; e++) {
        int2 p = g_csr[e];
        float wt = __int_as_float(p.y);
        float2 v = *(const float2*)(h + (size_t)p.x * 64 + lane * 2);
        acc.x = fmaf(wt, v.x, acc.x); acc.y = fmaf(wt, v.y, acc.y);
    }
    float2 bb = *(const float2*)(bias + lane * 2);
    acc.x += bb.x; acc.y += bb.y;
    if (RELU) { acc.x = fmaxf(acc.x, 0.f); acc.y = fmaxf(acc.y, 0.f); }
    *(float2*)(out + (size_t)w * 64 + lane * 2) = acc;
}

// ---------------- decode ----------------
__global__ __launch_bounds__(256)
void k_decode(const float* __restrict__ z, const int* __restrict__ eli,
              float* __restrict__ out) {
    int w    = (blockIdx.x * blockDim.x + threadIdx.x) >> 5;
    int lane = threadIdx.x & 31;
    if (w >= NLAB) return;
    int a = eli[w];
    int b = eli[NLAB + w];
    float2 za = *(const float2*)(z + (size_t)a * 64 + lane * 2);
    float2 zb = *(const float2*)(z + (size_t)b * 64 + lane * 2);
    float h0 = za.x * zb.x;
    float h1 = za.y * zb.y;
    float s  = h0 + h1;
    float q  = h0 * h0 + h1 * h1;
#pragma unroll
    for (int off = 16; off > 0; off >>= 1) {
        s += __shfl_xor_sync(0xFFFFFFFFu, s, off);
        q += __shfl_xor_sync(0xFFFFFFFFu, q, off);
    }
    float nrm = fmaxf(sqrtf(q), 1e-12f);
    float inv = 1.0f / nrm;
    *(float2*)(out + (size_t)w * 64 + lane * 2) = make_float2(h0 * inv, h1 * inv);
    if (lane == 0) out[(size_t)NLAB * 64 + w] = s;
}

// ---------------- launch ----------------
extern "C" void kernel_launch(void* const* d_in, const int* in_sizes, int n_in,
                              void* d_out, int out_size) {
    const float* x  = (const float*)d_in[0];
    const float* W1 = (const float*)d_in[1];
    const float* b1 = (const float*)d_in[2];
    const float* W2 = (const float*)d_in[3];
    const float* b2 = (const float*)d_in[4];
    const float* W3 = (const float*)d_in[5];
    const float* b3 = (const float*)d_in[6];
    const int*   ei  = (const int*)d_in[7];
    const int*   eli = (const int*)d_in[8];
    float* out = (float*)d_out;

    float* bufA = nullptr;
    float* bufB = nullptr;
    cudaGetSymbolAddress((void**)&bufA, g_bufA);
    cudaGetSymbolAddress((void**)&bufB, g_bufB);

    const int SMEM128 = (2 * 128 * 72 + 2 * 128 * 72) * 2;   // 73728 B
    const int SMEM64  = (2 * 128 * 72 + 2 * 64 * 72) * 2;    // 55296 B

    // One-time init: first call is the eager correctness run (not under
    // capture). Stream/event creation and func attributes happen here only.
    static cudaStream_t s2 = nullptr;
    static cudaEvent_t ev0 = nullptr, ev1 = nullptr;
    if (s2 == nullptr) {
        cudaStreamCreateWithFlags(&s2, cudaStreamNonBlocking);
        cudaEventCreateWithFlags(&ev0, cudaEventDisableTiming);
        cudaEventCreateWithFlags(&ev1, cudaEventDisableTiming);
        cudaFuncSetAttribute(k_mma_gemm<128>, cudaFuncAttributeMaxDynamicSharedMemorySize, SMEM128);
        cudaFuncSetAttribute(k_mma_gemm<64>,  cudaFuncAttributeMaxDynamicSharedMemorySize, SMEM64);
    }

    const int nscan = (NNODES + 1023) / 1024;             // 98
    const int gemm_grid  = (NNODES + 127) / 128;          // 782
    const int agg_grid   = (NNODES * 64 + 255) / 256;     // 25000 (2 warps/node)
    const int agg64_grid = (NNODES * 32 + 255) / 256;     // 12500
    const int dec_grid   = (NLAB * 32 + 255) / 256;       // 25000

    // Fork: CSR build on s2, GEMM1 on default stream (independent work).
    cudaEventRecord(ev0, 0);
    cudaStreamWaitEvent(s2, ev0, 0);

    k_init<<<(NNODES + 255) / 256, 256, 0, s2>>>();
    k_count<<<(NEDGES + 255) / 256, 256, 0, s2>>>(ei);
    k_dis<<<(NNODES + 255) / 256, 256, 0, s2>>>();
    k_scan_blocks<<<nscan, 1024, 0, s2>>>();
    k_scan_sums2<<<1, 128, 0, s2>>>(nscan);

    k_mma_gemm<128><<<gemm_grid, 256, SMEM128>>>(x, W1, bufB, NNODES);

    k_add_off<<<(NNODES + 255) / 256, 256, 0, s2>>>();
    k_fill_csr<<<(TOTE + 255) / 256, 256, 0, s2>>>(ei);
    cudaEventRecord(ev1, s2);
    cudaStreamWaitEvent(0, ev1, 0);

    k_aggregate128<true><<<agg_grid, 256>>>(bufB, b1, bufA);
    k_mma_gemm<128><<<gemm_grid, 256, SMEM128>>>(bufA, W2, bufB, NNODES);
    k_aggregate128<true><<<agg_grid, 256>>>(bufB, b2, bufA);
    k_mma_gemm<64><<<gemm_grid, 256, SMEM64>>>(bufA, W3, bufB, NNODES);
    k_aggregate64<false><<<agg64_grid, 256>>>(bufB, b3, bufA);
    k_decode<<<dec_grid, 256>>>(bufA, eli, out);
}

// round 9
// speedup vs baseline: 1.2146x; 1.0489x over previous
#include <cuda_runtime.h>
#include <cuda_bf16.h>
#include <math.h>
#include <stdint.h>

#define NNODES 100000
#define NEDGES 1600000
#define NLAB   200000
#define TOTE   (NEDGES + NNODES)

// ---------------- scratch (device globals; no allocation allowed) ----------------
__device__ int   g_deg[NNODES];
__device__ float g_dis[NNODES];
__device__ int   g_row[NNODES + 1];
__device__ int   g_cnt[NNODES];
__device__ int   g_bsum[128];
__device__ int2  g_csr[TOTE];            // packed (src, weight-bits)
__device__ float g_bufA[(size_t)NNODES * 128];
__device__ float g_bufB[(size_t)NNODES * 128];

// ---------------- warp-mma helpers (sm_80+ baseline ISA; no 'a' features) ----------------
__device__ __forceinline__ uint32_t smem_u32(const void* p) {
    uint32_t a;
    asm("{ .reg .u64 t; cvta.to.shared.u64 t, %1; cvt.u32.u64 %0, t; }" : "=r"(a) : "l"(p));
    return a;
}
__device__ __forceinline__ void ldsm_x4(uint32_t* r, uint32_t addr) {
    asm volatile("ldmatrix.sync.aligned.m8n8.x4.shared.b16 {%0,%1,%2,%3}, [%4];"
        : "=r"(r[0]), "=r"(r[1]), "=r"(r[2]), "=r"(r[3]) : "r"(addr));
}
__device__ __forceinline__ void mma_bf16(float* c, const uint32_t* a, const uint32_t* b) {
    asm volatile("mma.sync.aligned.m16n8k16.row.col.f32.bf16.bf16.f32 "
        "{%0,%1,%2,%3}, {%4,%5,%6,%7}, {%8,%9}, {%0,%1,%2,%3};"
        : "+f"(c[0]), "+f"(c[1]), "+f"(c[2]), "+f"(c[3])
        : "r"(a[0]), "r"(a[1]), "r"(a[2]), "r"(a[3]), "r"(b[0]), "r"(b[1]));
}

// ---------------- CSR build ----------------
__global__ void k_init(void) {
    int i = blockIdx.x * blockDim.x + threadIdx.x;
    if (i < NNODES) { g_deg[i] = 1; g_cnt[i] = 0; }
}
__global__ void k_count(const int* __restrict__ ei) {
    int e = blockIdx.x * blockDim.x + threadIdx.x;
    if (e < NEDGES) atomicAdd(&g_deg[ei[NEDGES + e]], 1);
}
__global__ void k_scan_blocks(void) {       // also computes g_dis (deg is final here)
    __shared__ int sh[1024];
    int i = blockIdx.x * 1024 + threadIdx.x;
    int v = (i < NNODES) ? g_deg[i] : 0;
    if (i < NNODES) g_dis[i] = rsqrtf((float)v);
    sh[threadIdx.x] = v;
    __syncthreads();
    for (int off = 1; off < 1024; off <<= 1) {
        int t = (threadIdx.x >= off) ? sh[threadIdx.x - off] : 0;
        __syncthreads();
        sh[threadIdx.x] += t;
        __syncthreads();
    }
    if (i < NNODES) g_row[i] = sh[threadIdx.x] - v;
    if (threadIdx.x == 1023) g_bsum[blockIdx.x] = sh[1023];
}
__global__ void k_scan_sums2(int nblocks) {     // parallel 128-wide scan
    __shared__ int sh[128];
    int t = threadIdx.x;
    int v = (t < nblocks) ? g_bsum[t] : 0;
    sh[t] = v;
    __syncthreads();
    for (int off = 1; off < 128; off <<= 1) {
        int u = (t >= off) ? sh[t - off] : 0;
        __syncthreads();
        sh[t] += u;
        __syncthreads();
    }
    if (t < nblocks) g_bsum[t] = sh[t] - v;     // exclusive
}
__global__ void k_add_off(void) {
    int i = blockIdx.x * blockDim.x + threadIdx.x;
    if (i < NNODES) g_row[i] += g_bsum[i >> 10];
    if (i == 0) g_row[NNODES] = TOTE;
}
__global__ void k_fill_csr(const int* __restrict__ ei) {
    int idx = blockIdx.x * blockDim.x + threadIdx.x;
    if (idx >= TOTE) return;
    int s, d;
    if (idx < NEDGES) { s = ei[idx]; d = ei[NEDGES + idx]; }
    else              { s = d = idx - NEDGES; }
    int pos = g_row[d] + atomicAdd(&g_cnt[d], 1);
    float w = g_dis[s] * g_dis[d];
    g_csr[pos] = make_int2(s, __float_as_int(w));
}

// ---------------- mma.sync bf16 GEMM: O[M,BN] = X[M,128] @ W[128,BN] ----------------
// 2-way bf16 split: O = Ah@Bh + Ah@Bl + Al@Bh (residual ~2^-16).
// K staged in two 64-wide chunks -> smem 72KB -> 2 CTAs/SM. LDA=72 (144B rows,
// conflict-free ldmatrix).
template<int BN>
__global__ __launch_bounds__(256, 2)
void k_mma_gemm(const float* __restrict__ X, const float* __restrict__ W,
                float* __restrict__ O, int M) {
    constexpr int LDA = 72;
    constexpr int ASZ = 128 * LDA;
    constexpr int BSZ = BN * LDA;
    constexpr int WM = (BN == 128) ? 2 : 4;
    constexpr int MT = 128 / WM / 16;
    constexpr int NT = 4;

    extern __shared__ __align__(16) __nv_bfloat16 smx[];
    __nv_bfloat16* Ah = smx;
    __nv_bfloat16* Al = Ah + ASZ;
    __nv_bfloat16* Bh = Al + ASZ;
    __nv_bfloat16* Bl = Bh + BSZ;

    int tid = threadIdx.x, wid = tid >> 5, lane = tid & 31;
    int brow = blockIdx.x * 128;

    int wm = wid % WM, wn = wid / WM;
    int rows0 = wm * (MT * 16);
    int col0  = wn * 32;

    int a_r = rows0 + (lane & 15);
    int a_c = (lane & 16) >> 1;
    int b_r = col0 + (lane & 7) + ((lane & 16) >> 1);
    int b_c = (lane & 8);
    uint32_t ah_base = smem_u32(Ah) + (uint32_t)(a_r * LDA + a_c) * 2;
    uint32_t al_base = smem_u32(Al) + (uint32_t)(a_r * LDA + a_c) * 2;
    uint32_t bh_base = smem_u32(Bh) + (uint32_t)(b_r * LDA + b_c) * 2;
    uint32_t bl_base = smem_u32(Bl) + (uint32_t)(b_r * LDA + b_c) * 2;

    float acc[MT][NT][4];
#pragma unroll
    for (int m = 0; m < MT; m++)
#pragma unroll
        for (int n = 0; n < NT; n++)
#pragma unroll
            for (int q = 0; q < 4; q++) acc[m][n][q] = 0.f;

    for (int kc = 0; kc < 128; kc += 64) {
        for (int idx = tid; idx < 128 * 16; idx += 256) {
            int r = idx >> 4, c4 = (idx & 15) * 4;
            float4 v = make_float4(0.f, 0.f, 0.f, 0.f);
            int gr = brow + r;
            if (gr < M) v = *(const float4*)(X + (size_t)gr * 128 + kc + c4);
            float f[4] = {v.x, v.y, v.z, v.w};
            __nv_bfloat16 h[4], l[4];
#pragma unroll
            for (int j = 0; j < 4; j++) {
                h[j] = __float2bfloat16_rn(f[j]);
                l[j] = __float2bfloat16_rn(f[j] - __bfloat162float(h[j]));
            }
            int o = r * LDA + c4;
            *(__nv_bfloat162*)(Ah + o)     = __nv_bfloat162(h[0], h[1]);
            *(__nv_bfloat162*)(Ah + o + 2) = __nv_bfloat162(h[2], h[3]);
            *(__nv_bfloat162*)(Al + o)     = __nv_bfloat162(l[0], l[1]);
            *(__nv_bfloat162*)(Al + o + 2) = __nv_bfloat162(l[2], l[3]);
        }
        for (int idx = tid; idx < 16 * BN; idx += 256) {
            int n  = idx % BN;
            int k0 = (idx / BN) * 4;
            float f[4];
#pragma unroll
            for (int j = 0; j < 4; j++) f[j] = W[(size_t)(kc + k0 + j) * BN + n];
            __nv_bfloat16 h[4], l[4];
#pragma unroll
            for (int j = 0; j < 4; j++) {
                h[j] = __float2bfloat16_rn(f[j]);
                l[j] = __float2bfloat16_rn(f[j] - __bfloat162float(h[j]));
            }
            int o = n * LDA + k0;
            *(__nv_bfloat162*)(Bh + o)     = __nv_bfloat162(h[0], h[1]);
            *(__nv_bfloat162*)(Bh + o + 2) = __nv_bfloat162(h[2], h[3]);
            *(__nv_bfloat162*)(Bl + o)     = __nv_bfloat162(l[0], l[1]);
            *(__nv_bfloat162*)(Bl + o + 2) = __nv_bfloat162(l[2], l[3]);
        }
        __syncthreads();

#pragma unroll
        for (int ks = 0; ks < 4; ks++) {
            uint32_t koff = (uint32_t)(ks * 16) * 2;
            uint32_t ah[MT][4], al[MT][4], bh[2][4], bl[2][4];
#pragma unroll
            for (int m = 0; m < MT; m++) {
                uint32_t moff = (uint32_t)(m * 16 * LDA) * 2;
                ldsm_x4(ah[m], ah_base + moff + koff);
                ldsm_x4(al[m], al_base + moff + koff);
            }
#pragma unroll
            for (int p = 0; p < 2; p++) {
                uint32_t poff = (uint32_t)(p * 16 * LDA) * 2;
                ldsm_x4(bh[p], bh_base + poff + koff);
                ldsm_x4(bl[p], bl_base + poff + koff);
            }
#pragma unroll
            for (int m = 0; m < MT; m++) {
#pragma unroll
                for (int p = 0; p < 2; p++) {
                    mma_bf16(acc[m][2 * p],     ah[m], &bh[p][0]);
                    mma_bf16(acc[m][2 * p],     ah[m], &bl[p][0]);
                    mma_bf16(acc[m][2 * p],     al[m], &bh[p][0]);
                    mma_bf16(acc[m][2 * p + 1], ah[m], &bh[p][2]);
                    mma_bf16(acc[m][2 * p + 1], ah[m], &bl[p][2]);
                    mma_bf16(acc[m][2 * p + 1], al[m], &bh[p][2]);
                }
            }
        }
        __syncthreads();
    }

    int gid  = lane >> 2;
    int quad = lane & 3;
#pragma unroll
    for (int m = 0; m < MT; m++) {
        int r0 = brow + rows0 + m * 16 + gid;
#pragma unroll
        for (int n = 0; n < NT; n++) {
            int c = col0 + n * 8 + quad * 2;
            if (r0 < M)
                *(float2*)(O + (size_t)r0 * BN + c) = make_float2(acc[m][n][0], acc[m][n][1]);
            if (r0 + 8 < M)
                *(float2*)(O + (size_t)(r0 + 8) * BN + c) = make_float2(acc[m][n][2], acc[m][n][3]);
        }
    }
}

// ---------------- aggregation (128-wide): 2 warps per node, 8-deep pipeline ----------------
template<bool RELU>
__global__ __launch_bounds__(256)
void k_aggregate128(const float* __restrict__ h, const float* __restrict__ bias,
                    float* __restrict__ out) {
    int gw   = (blockIdx.x * blockDim.x + threadIdx.x) >> 5;
    int lane = threadIdx.x & 31;
    int node = gw >> 1;
    int half = gw & 1;
    if (node >= NNODES) return;
    const float* hh = h + half * 64;
    int e = g_row[node], end = g_row[node + 1];
    float2 acc = make_float2(0.f, 0.f);
    for (; e + 8 <= end; e += 8) {
        int2 p[8];
#pragma unroll
        for (int j = 0; j < 8; j++) p[j] = g_csr[e + j];
        float2 v[8];
#pragma unroll
        for (int j = 0; j < 8; j++) v[j] = *(const float2*)(hh + (size_t)p[j].x * 128 + lane * 2);
#pragma unroll
        for (int j = 0; j < 8; j++) {
            float wt = __int_as_float(p[j].y);
            acc.x = fmaf(wt, v[j].x, acc.x);
            acc.y = fmaf(wt, v[j].y, acc.y);
        }
    }
    for (; e + 4 <= end; e += 4) {
        int2 p[4];
#pragma unroll
        for (int j = 0; j < 4; j++) p[j] = g_csr[e + j];
        float2 v[4];
#pragma unroll
        for (int j = 0; j < 4; j++) v[j] = *(const float2*)(hh + (size_t)p[j].x * 128 + lane * 2);
#pragma unroll
        for (int j = 0; j < 4; j++) {
            float wt = __int_as_float(p[j].y);
            acc.x = fmaf(wt, v[j].x, acc.x);
            acc.y = fmaf(wt, v[j].y, acc.y);
        }
    }
    for (; e < end; e++) {
        int2 p = g_csr[e];
        float wt = __int_as_float(p.y);
        float2 v = *(const float2*)(hh + (size_t)p.x * 128 + lane * 2);
        acc.x = fmaf(wt, v.x, acc.x); acc.y = fmaf(wt, v.y, acc.y);
    }
    float2 bb = *(const float2*)(bias + half * 64 + lane * 2);
    acc.x += bb.x; acc.y += bb.y;
    if (RELU) { acc.x = fmaxf(acc.x, 0.f); acc.y = fmaxf(acc.y, 0.f); }
    *(float2*)(out + (size_t)node * 128 + half * 64 + lane * 2) = acc;
}

template<bool RELU>
__global__ __launch_bounds__(256)
void k_aggregate64(const float* __restrict__ h, const float* __restrict__ bias,
                   float* __restrict__ out) {
    int w    = (blockIdx.x * blockDim.x + threadIdx.x) >> 5;
    int lane = threadIdx.x & 31;
    if (w >= NNODES) return;
    int e = g_row[w], end = g_row[w + 1];
    float2 acc = make_float2(0.f, 0.f);
    for (; e + 8 <= end; e += 8) {
        int2 p[8];
#pragma unroll
        for (int j = 0; j < 8; j++) p[j] = g_csr[e + j];
        float2 v[8];
#pragma unroll
        for (int j = 0; j < 8; j++) v[j] = *(const float2*)(h + (size_t)p[j].x * 64 + lane * 2);
#pragma unroll
        for (int j = 0; j < 8; j++) {
            float wt = __int_as_float(p[j].y);
            acc.x = fmaf(wt, v[j].x, acc.x);
            acc.y = fmaf(wt, v[j].y, acc.y);
        }
    }
    for (; e + 4 <= end; e += 4) {
        int2 p[4];
#pragma unroll
        for (int j = 0; j < 4; j++) p[j] = g_csr[e + j];
        float2 v[4];
#pragma unroll
        for (int j = 0; j < 4; j++) v[j] = *(const float2*)(h + (size_t)p[j].x * 64 + lane * 2);
#pragma unroll
        for (int j = 0; j < 4; j++) {
            float wt = __int_as_float(p[j].y);
            acc.x = fmaf(wt, v[j].x, acc.x);
            acc.y = fmaf(wt, v[j].y, acc.y);
        }
    }
    for (; e < end; e++) {
        int2 p = g_csr[e];
        float wt = __int_as_float(p.y);
        float2 v = *(const float2*)(h + (size_t)p.x * 64 + lane * 2);
        acc.x = fmaf(wt, v.x, acc.x); acc.y = fmaf(wt, v.y, acc.y);
    }
    float2 bb = *(const float2*)(bias + lane * 2);
    acc.x += bb.x; acc.y += bb.y;
    if (RELU) { acc.x = fmaxf(acc.x, 0.f); acc.y = fmaxf(acc.y, 0.f); }
    *(float2*)(out + (size_t)w * 64 + lane * 2) = acc;
}

// ---------------- decode (s,q packed into one 64-bit shfl chain) ----------------
__global__ __launch_bounds__(256)
void k_decode(const float* __restrict__ z, const int* __restrict__ eli,
              float* __restrict__ out) {
    int w    = (blockIdx.x * blockDim.x + threadIdx.x) >> 5;
    int lane = threadIdx.x & 31;
    if (w >= NLAB) return;
    int a = eli[w];
    int b = eli[NLAB + w];
    float2 za = *(const float2*)(z + (size_t)a * 64 + lane * 2);
    float2 zb = *(const float2*)(z + (size_t)b * 64 + lane * 2);
    float h0 = za.x * zb.x;
    float h1 = za.y * zb.y;
    float s  = h0 + h1;
    float q  = h0 * h0 + h1 * h1;
#pragma unroll
    for (int off = 16; off > 0; off >>= 1) {
        unsigned long long pk;
        asm("mov.b64 %0, {%1, %2};" : "=l"(pk) : "f"(s), "f"(q));
        unsigned long long other = __shfl_xor_sync(0xFFFFFFFFu, pk, off);
        float os, oq;
        asm("mov.b64 {%0, %1}, %2;" : "=f"(os), "=f"(oq) : "l"(other));
        s += os; q += oq;
    }
    float nrm = fmaxf(sqrtf(q), 1e-12f);
    float inv = 1.0f / nrm;
    *(float2*)(out + (size_t)w * 64 + lane * 2) = make_float2(h0 * inv, h1 * inv);
    if (lane == 0) out[(size_t)NLAB * 64 + w] = s;
}

// ---------------- launch ----------------
extern "C" void kernel_launch(void* const* d_in, const int* in_sizes, int n_in,
                              void* d_out, int out_size) {
    const float* x  = (const float*)d_in[0];
    const float* W1 = (const float*)d_in[1];
    const float* b1 = (const float*)d_in[2];
    const float* W2 = (const float*)d_in[3];
    const float* b2 = (const float*)d_in[4];
    const float* W3 = (const float*)d_in[5];
    const float* b3 = (const float*)d_in[6];
    const int*   ei  = (const int*)d_in[7];
    const int*   eli = (const int*)d_in[8];
    float* out = (float*)d_out;

    float* bufA = nullptr;
    float* bufB = nullptr;
    cudaGetSymbolAddress((void**)&bufA, g_bufA);
    cudaGetSymbolAddress((void**)&bufB, g_bufB);

    const int SMEM128 = (2 * 128 * 72 + 2 * 128 * 72) * 2;   // 73728 B
    const int SMEM64  = (2 * 128 * 72 + 2 * 64 * 72) * 2;    // 55296 B

    // One-time init: first call is the eager correctness run (not under
    // capture). Stream/event creation and func attributes happen here only.
    static cudaStream_t s2 = nullptr;
    static cudaEvent_t ev0 = nullptr, ev1 = nullptr;
    if (s2 == nullptr) {
        cudaStreamCreateWithFlags(&s2, cudaStreamNonBlocking);
        cudaEventCreateWithFlags(&ev0, cudaEventDisableTiming);
        cudaEventCreateWithFlags(&ev1, cudaEventDisableTiming);
        cudaFuncSetAttribute(k_mma_gemm<128>, cudaFuncAttributeMaxDynamicSharedMemorySize, SMEM128);
        cudaFuncSetAttribute(k_mma_gemm<64>,  cudaFuncAttributeMaxDynamicSharedMemorySize, SMEM64);
    }

    const int nscan = (NNODES + 1023) / 1024;             // 98
    const int gemm_grid  = (NNODES + 127) / 128;          // 782
    const int agg_grid   = (NNODES * 64 + 255) / 256;     // 25000 (2 warps/node)
    const int agg64_grid = (NNODES * 32 + 255) / 256;     // 12500
    const int dec_grid   = (NLAB * 32 + 255) / 256;       // 25000

    // Fork: CSR build on s2, GEMM1 on default stream (independent work).
    cudaEventRecord(ev0, 0);
    cudaStreamWaitEvent(s2, ev0, 0);

    k_init<<<(NNODES + 255) / 256, 256, 0, s2>>>();
    k_count<<<(NEDGES + 255) / 256, 256, 0, s2>>>(ei);
    k_scan_blocks<<<nscan, 1024, 0, s2>>>();
    k_scan_sums2<<<1, 128, 0, s2>>>(nscan);

    k_mma_gemm<128><<<gemm_grid, 256, SMEM128>>>(x, W1, bufB, NNODES);

    k_add_off<<<(NNODES + 255) / 256, 256, 0, s2>>>();
    k_fill_csr<<<(TOTE + 255) / 256, 256, 0, s2>>>(ei);
    cudaEventRecord(ev1, s2);
    cudaStreamWaitEvent(0, ev1, 0);

    k_aggregate128<true><<<agg_grid, 256>>>(bufB, b1, bufA);
    k_mma_gemm<128><<<gemm_grid, 256, SMEM128>>>(bufA, W2, bufB, NNODES);
    k_aggregate128<true><<<agg_grid, 256>>>(bufB, b2, bufA);
    k_mma_gemm<64><<<gemm_grid, 256, SMEM64>>>(bufA, W3, bufB, NNODES);
    k_aggregate64<false><<<agg64_grid, 256>>>(bufB, b3, bufA);
    k_decode<<<dec_grid, 256>>>(bufA, eli, out);
}